// round 15
// baseline (speedup 1.0000x reference)
#include <cuda_runtime.h>
#include <cuda_fp16.h>
#include <cstdint>

// VectorQuantizer: N=65536 rows, D=256, K=1024 codes.
// Pass 1: HFMA2 (half2) GEMM-argmin at 2x FFMA rate. margin < 0.5 -> flag.
// vq_fix (batched two-tier): 8 flagged rows per block share one e-stream.
//   Tier 1: fp32 dots (1 float4 of e per d serves 8 rows). Tier 2 (rare,
//   margin < 1e-3): compensated-fp32 exact + TIE_EPS=7.5e-5 window pick-lowest
//   (R6-calibrated). Patch out + loss.

#define N_ROWS   65536
#define DIM      256
#define K_CODES  1024
#define BM       64
#define FLAG_THR 0.5f
#define TIE_EPS  7.5e-5
#define AMB_CAP  32768
#define RB       8             // rows per fix block
#define ASTR2    68            // xs2 stride in half2

__device__ double  g_loss_acc;
__device__ float   g_enorm[K_CODES];
__device__ double  g_enorm_d[K_CODES];
__device__ float   g_eT[K_CODES * DIM];      // e transposed [k][d]
__device__ __half2 g_e2[128 * K_CODES];      // half2 packed [d2][k]
__device__ int     g_idx[N_ROWS];
__device__ int     g_amb[AMB_CAP];
__device__ int     g_amb_count;

// smem FLOAT offsets for vq_main (half2 = 4 bytes = 1 float)
#define OFF_XS2  0          // 128 d2 x 68 half2 = 8704 f
#define OFF_ES2  8704       // 32 d2 x 64 codes half2 = 2048 f
#define OFF_SN   10752
#define OFF_RV   10816
#define OFF_RS   11840
#define OFF_RI   12864
#define OFF_LRED 13888
#define SMEM_FLOATS 13896
#define SMEM_BYTES  (SMEM_FLOATS * 4)

// ---------------------------------------------------------------------------
__global__ void vq_prep(const float* __restrict__ e) {
    int b = blockIdx.x;
    if (b < 256) {
        int d = b;
        for (int k = threadIdx.x; k < K_CODES; k += 256)
            g_eT[k * DIM + d] = e[d * K_CODES + k];
    } else if (b < 260) {
        int k = (b - 256) * 256 + threadIdx.x;
        double s = 0.0;
        for (int d = 0; d < DIM; d++) {
            double v = (double)e[d * K_CODES + k];
            s += v * v;
        }
        g_enorm[k]   = (float)s;
        g_enorm_d[k] = s;
        if (b == 256 && threadIdx.x == 0) {
            g_loss_acc = 0.0; g_amb_count = 0;
        }
    } else {
        int d2 = b - 260;
        for (int k = threadIdx.x; k < K_CODES; k += 256)
            g_e2[d2 * K_CODES + k] = __floats2half2_rn(
                e[(2 * d2) * K_CODES + k], e[(2 * d2 + 1) * K_CODES + k]);
    }
}

// ---------------------------------------------------------------------------
__global__ void __launch_bounds__(256) vq_main(const float* __restrict__ x,
                                               float* __restrict__ out) {
    extern __shared__ float sm[];
    __half2* xs2  = (__half2*)(sm + OFF_XS2);
    __half2* es2  = (__half2*)(sm + OFF_ES2);
    float*   snorm = sm + OFF_SN;
    float*   rv   = sm + OFF_RV;
    float*   rs   = sm + OFF_RS;
    int*     ri   = (int*)(sm + OFF_RI);
    float*   lred = sm + OFF_LRED;

    const int tid  = threadIdx.x;
    const int lane = tid & 31;
    const int wid  = tid >> 5;
    const int tx   = tid & 15;
    const int ty   = tid >> 4;
    const int tx4  = tx * 4;
    const int ty4  = ty * 4;
    const int row0 = blockIdx.x * BM;
    const float* xblk = x + (size_t)row0 * DIM;

    #pragma unroll
    for (int it = 0; it < 16; it++) {
        int i  = it * 256 + tid;
        int r  = i >> 6;
        int c4 = i & 63;
        float4 v = ((const float4*)(xblk + (size_t)r * DIM))[c4];
        int d2 = c4 * 2;
        xs2[d2 * ASTR2 + r]       = __floats2half2_rn(v.x, v.y);
        xs2[(d2 + 1) * ASTR2 + r] = __floats2half2_rn(v.z, v.w);
    }

    float bestv[4], secv[4];
    int   besti[4];
    #pragma unroll
    for (int i = 0; i < 4; i++) { bestv[i] = 3.4e38f; secv[i] = 3.4e38f; besti[i] = 0; }

    float facc[4][4];
    uint4 pf[2];
    const int d2l = tid >> 3, cg = tid & 7;

    {
        const uint4* p = (const uint4*)&g_e2[(size_t)d2l * K_CODES + cg * 8];
        pf[0] = p[0]; pf[1] = p[1];
    }

    for (int s = 0; s < 64; s++) {
        const int tile = s >> 2, dk = s & 3;
        const int c0 = tile * 64;

        __syncthreads();
        {
            uint4* q = (uint4*)&es2[d2l * 64 + cg * 8];
            q[0] = pf[0]; q[1] = pf[1];
        }
        if (dk == 0 && tid < 64) snorm[tid] = g_enorm[c0 + tid];

        if (s + 1 < 64) {
            int t1 = (s + 1) >> 2, dk1 = (s + 1) & 3;
            const uint4* p = (const uint4*)&g_e2[
                (size_t)(dk1 * 32 + d2l) * K_CODES + t1 * 64 + cg * 8];
            pf[0] = p[0]; pf[1] = p[1];
        }
        __syncthreads();

        if (dk == 0) {
            #pragma unroll
            for (int i = 0; i < 4; i++)
                #pragma unroll
                for (int j = 0; j < 4; j++) facc[i][j] = 0.f;
        }

        __half2 acc2[4][4];
        #pragma unroll
        for (int i = 0; i < 4; i++)
            #pragma unroll
            for (int j = 0; j < 4; j++) acc2[i][j] = __floats2half2_rn(0.f, 0.f);

        const int dbase = dk * 32;
        #pragma unroll 8
        for (int d2 = 0; d2 < 32; d2++) {
            uint4 au = *(const uint4*)&xs2[(dbase + d2) * ASTR2 + ty4];
            uint4 bu = *(const uint4*)&es2[d2 * 64 + tx4];
            __half2 ax[4], bx[4];
            *(uint4*)ax = au;
            *(uint4*)bx = bu;
            #pragma unroll
            for (int i = 0; i < 4; i++)
                #pragma unroll
                for (int j = 0; j < 4; j++)
                    acc2[i][j] = __hfma2(ax[i], bx[j], acc2[i][j]);
        }

        #pragma unroll
        for (int i = 0; i < 4; i++)
            #pragma unroll
            for (int j = 0; j < 4; j++)
                facc[i][j] += __low2float(acc2[i][j]) + __high2float(acc2[i][j]);

        if (dk == 3) {
            #pragma unroll
            for (int j = 0; j < 4; j++) {
                float n = snorm[tx4 + j];
                int  ci = c0 + tx4 + j;
                #pragma unroll
                for (int i = 0; i < 4; i++) {
                    float dist = fmaf(-2.f, facc[i][j], n);
                    if (dist < bestv[i]) {
                        secv[i] = bestv[i]; bestv[i] = dist; besti[i] = ci;
                    } else if (dist < secv[i]) {
                        secv[i] = dist;
                    }
                }
            }
        }
    }

    __syncthreads();
    #pragma unroll
    for (int i = 0; i < 4; i++) {
        int row = ty4 + i;
        rv[row * 16 + tx] = bestv[i];
        rs[row * 16 + tx] = secv[i];
        ri[row * 16 + tx] = besti[i];
    }
    __syncthreads();
    if (tid < BM) {
        int row = tid;
        float m1v = 3.4e38f, m2v = 3.4e38f;
        int m1i = 0;
        #pragma unroll
        for (int t = 0; t < 16; t++) {
            float v  = rv[row * 16 + t];
            int   i2 = ri[row * 16 + t];
            float s2 = rs[row * 16 + t];
            if (v < m1v) {
                if (m1v < m2v) m2v = m1v;
                m1v = v; m1i = i2;
            } else if (v < m2v) m2v = v;
            if (s2 < m2v) m2v = s2;
        }
        m1i &= (K_CODES - 1);
        int grow = row0 + row;
        g_idx[grow] = m1i;
        ri[row * 16] = m1i;
        if (!(m2v - m1v >= FLAG_THR)) {
            int slot = atomicAdd(&g_amb_count, 1);
            if (slot < AMB_CAP) g_amb[slot] = grow;
        }
    }
    __syncthreads();

    float local = 0.f;
    #pragma unroll
    for (int rr = 0; rr < BM / 8; rr++) {
        int row = wid * 8 + rr;
        int idx = ri[row * 16] & (K_CODES - 1);
        const float* esrc = g_eT + (size_t)idx * DIM;
        const float* xrow = xblk + (size_t)row * DIM;
        float* orow = out + (size_t)(row0 + row) * DIM;
        #pragma unroll
        for (int kk = 0; kk < 8; kk++) {
            int d = kk * 32 + lane;
            float q  = esrc[d];
            float xv = xrow[d];
            float dq = q - xv;
            local += dq * dq;
            orow[d] = xv + dq;
        }
    }
    #pragma unroll
    for (int off = 16; off; off >>= 1)
        local += __shfl_xor_sync(0xffffffffu, local, off);
    if (lane == 0) lred[wid] = local;
    __syncthreads();
    if (tid == 0) {
        float ssum = 0.f;
        #pragma unroll
        for (int w = 0; w < 8; w++) ssum += lred[w];
        atomicAdd(&g_loss_acc, (double)ssum);
    }
}

// ---------------------------------------------------------------------------
// vq_fix batched: RB flagged rows share one pass over e. Tier-1 fp32; tier-2
// compensated + TIE_EPS window per near-tie row only. Patch out + loss.
__global__ void __launch_bounds__(256) vq_fix(const float* __restrict__ x,
                                              const float* __restrict__ e,
                                              float* __restrict__ out) {
    __shared__ float  xr[RB * DIM];
    __shared__ int    rows_s[RB];
    __shared__ float  frb[256], frs[256];
    __shared__ int    fri[256];
    __shared__ double sdd[256];
    __shared__ double svv[256];
    __shared__ int    sii[256];
    __shared__ double s_minv;

    const int tid = threadIdx.x;
    int total = g_amb_count; if (total > AMB_CAP) total = AMB_CAP;
    int ngroups = (total + RB - 1) / RB;

    for (int grp = blockIdx.x; grp < ngroups; grp += gridDim.x) {
        int base = grp * RB;
        int rcnt = total - base; if (rcnt > RB) rcnt = RB;

        if (tid < RB) rows_s[tid] = g_amb[base + (tid < rcnt ? tid : 0)];
        __syncthreads();
        for (int i = tid; i < RB * DIM; i += 256) {
            int r = i >> 8;
            xr[i] = (r < rcnt) ? x[(size_t)rows_s[r] * DIM + (i & 255)] : 0.f;
        }
        __syncthreads();

        // ---- tier 1: shared e-stream, 8 rows x 4 codes per thread ----
        float acc[RB][4];
        #pragma unroll
        for (int r = 0; r < RB; r++)
            #pragma unroll
            for (int j = 0; j < 4; j++) acc[r][j] = 0.f;

        const float* ebase = e + (size_t)tid * 4;
        #pragma unroll 4
        for (int d = 0; d < DIM; d++) {
            float4 ev = *(const float4*)(ebase + (size_t)d * K_CODES);
            #pragma unroll
            for (int r = 0; r < RB; r++) {
                float xv = xr[r * DIM + d];
                acc[r][0] = fmaf(xv, ev.x, acc[r][0]);
                acc[r][1] = fmaf(xv, ev.y, acc[r][1]);
                acc[r][2] = fmaf(xv, ev.z, acc[r][2]);
                acc[r][3] = fmaf(xv, ev.w, acc[r][3]);
            }
        }

        // ---- per-row: reduce, maybe tier-2, patch ----
        for (int r = 0; r < rcnt; r++) {
            int row = rows_s[r];
            float dj[4];
            #pragma unroll
            for (int j = 0; j < 4; j++)
                dj[j] = fmaf(-2.f, acc[r][j], g_enorm[tid * 4 + j]);

            float b = 3.4e38f, sv = 3.4e38f; int bi = 0;
            #pragma unroll
            for (int j = 0; j < 4; j++) {
                int k = tid * 4 + j;
                if (dj[j] < b) { sv = b; b = dj[j]; bi = k; }
                else if (dj[j] < sv) sv = dj[j];
            }
            frb[tid] = b; frs[tid] = sv; fri[tid] = bi;
            __syncthreads();
            for (int off = 128; off; off >>= 1) {
                if (tid < off) {
                    float b2 = frb[tid + off], s2v = frs[tid + off];
                    int   i2 = fri[tid + off];
                    float b1 = frb[tid], s1v = frs[tid];
                    int   i1 = fri[tid];
                    if (b2 < b1 || (b2 == b1 && i2 < i1)) {
                        frb[tid] = b2; fri[tid] = i2; frs[tid] = fminf(b1, s2v);
                    } else {
                        frs[tid] = fminf(s1v, b2);
                    }
                }
                __syncthreads();
            }
            float margin = frs[0] - frb[0];
            int newIdx = fri[0] & (K_CODES - 1);
            __syncthreads();

            if (!(margin >= 1e-3f)) {     // tier 2 — rare
                sdd[tid] = (double)xr[r * DIM + tid] * (double)xr[r * DIM + tid];
                __syncthreads();
                for (int off = 128; off; off >>= 1) {
                    if (tid < off) sdd[tid] += sdd[tid + off];
                    __syncthreads();
                }
                double xn = sdd[0];
                __syncthreads();

                float s[4] = {0.f, 0.f, 0.f, 0.f};
                float c[4] = {0.f, 0.f, 0.f, 0.f};
                #pragma unroll 4
                for (int d = 0; d < DIM; d++) {
                    float xv = xr[r * DIM + d];
                    float4 ev = *(const float4*)(ebase + (size_t)d * K_CODES);
                    float evs[4] = {ev.x, ev.y, ev.z, ev.w};
                    #pragma unroll
                    for (int j = 0; j < 4; j++) {
                        float p  = xv * evs[j];
                        float e1 = fmaf(xv, evs[j], -p);
                        float t  = s[j] + p;
                        float z  = t - s[j];
                        float e2 = (s[j] - (t - z)) + (p - z);
                        s[j] = t; c[j] += e1 + e2;
                    }
                }
                double dist[4];
                #pragma unroll
                for (int j = 0; j < 4; j++)
                    dist[j] = xn + g_enorm_d[tid * 4 + j]
                            - 2.0 * ((double)s[j] + (double)c[j]);

                double bv = 1e300; int bi2 = 0x7fffffff;
                #pragma unroll
                for (int j = 0; j < 4; j++) {
                    int k = tid * 4 + j;
                    if (dist[j] < bv || (dist[j] == bv && k < bi2)) { bv = dist[j]; bi2 = k; }
                }
                svv[tid] = bv; sii[tid] = bi2;
                __syncthreads();
                for (int off = 128; off; off >>= 1) {
                    if (tid < off) {
                        double v2 = svv[tid + off]; int i2 = sii[tid + off];
                        if (v2 < svv[tid] || (v2 == svv[tid] && i2 < sii[tid])) {
                            svv[tid] = v2; sii[tid] = i2;
                        }
                    }
                    __syncthreads();
                }
                if (tid == 0) s_minv = svv[0];
                __syncthreads();
                double minv = s_minv;

                int cand = 0x7fffffff;
                #pragma unroll
                for (int j = 0; j < 4; j++) {
                    int k = tid * 4 + j;
                    if (dist[j] <= minv + TIE_EPS && k < cand) cand = k;
                }
                sii[tid] = cand;
                __syncthreads();
                for (int off = 128; off; off >>= 1) {
                    if (tid < off) { if (sii[tid + off] < sii[tid]) sii[tid] = sii[tid + off]; }
                    __syncthreads();
                }
                newIdx = sii[0] & (K_CODES - 1);
                __syncthreads();
            }

            int oldIdx = g_idx[row];
            if (newIdx != oldIdx) {   // uniform across block
                float xv = xr[r * DIM + tid];
                float qn = g_eT[(size_t)newIdx * DIM + tid];
                float qo = g_eT[(size_t)oldIdx * DIM + tid];
                out[(size_t)row * DIM + tid] = xv + (qn - xv);
                double dn = (double)(qn - xv), dl = (double)(qo - xv);
                sdd[tid] = dn * dn - dl * dl;
                __syncthreads();
                for (int off = 128; off; off >>= 1) {
                    if (tid < off) sdd[tid] += sdd[tid + off];
                    __syncthreads();
                }
                if (tid == 0) atomicAdd(&g_loss_acc, sdd[0]);
            }
            __syncthreads();
        }
    }
}

// ---------------------------------------------------------------------------
__global__ void vq_finish(float* __restrict__ out) {
    const double nd = (double)N_ROWS * (double)DIM;
    out[(size_t)N_ROWS * DIM] = (float)(1.25 * g_loss_acc / nd);
}

// ---------------------------------------------------------------------------
extern "C" void kernel_launch(void* const* d_in, const int* in_sizes, int n_in,
                              void* d_out, int out_size) {
    const float* x = (const float*)d_in[0];
    const float* e = (const float*)d_in[1];
    if (n_in >= 2 && in_sizes[0] == K_CODES * DIM && in_sizes[1] == N_ROWS * DIM) {
        e = (const float*)d_in[0];
        x = (const float*)d_in[1];
    }
    float* out = (float*)d_out;

    cudaFuncSetAttribute(vq_main, cudaFuncAttributeMaxDynamicSharedMemorySize, SMEM_BYTES);

    vq_prep<<<388, 256>>>(e);
    vq_main<<<N_ROWS / BM, 256, SMEM_BYTES>>>(x, out);
    vq_fix<<<1024, 256>>>(x, e, out);
    if (out_size > N_ROWS * DIM) vq_finish<<<1, 1>>>(out);
}

// round 16
// speedup vs baseline: 1.1078x; 1.1078x over previous
#include <cuda_runtime.h>
#include <cstdint>

// VectorQuantizer: N=65536 rows, D=256, K=1024 codes.
// Pass 1: int8 dp4a GEMM-argmin (4 MAC/lane/instr). x,e quantized with fixed
//   scale 4.8/127 (clamped). dist = ||e||^2 - 2*s^2*dot_int. margin < 3.0 -> flag.
// vq_fix (batched two-tier): 8 rows share one e-stream; tier-1 fp32; tier-2
//   (margin<1e-3) compensated-fp32 exact + TIE_EPS=7.5e-5 window pick-lowest
//   (R6-calibrated). Patch out + loss.

#define N_ROWS   65536
#define DIM      256
#define K_CODES  1024
#define BM       64
#define FLAG_THR 3.0f
#define TIE_EPS  7.5e-5
#define AMB_CAP  65536
#define RB       8
#define XQSTR    68            // xsq stride in uint32

#define QMAX   4.8f
#define QS     (127.0f / QMAX)
#define SINV   (QMAX / 127.0f)
#define SCALE2 (2.0f * SINV * SINV)

__device__ double   g_loss_acc;
__device__ float    g_enorm[K_CODES];
__device__ double   g_enorm_d[K_CODES];
__device__ float    g_eT[K_CODES * DIM];     // e transposed [k][d]
__device__ uint32_t g_eq[64 * K_CODES];      // int8-packed e [d4][k]
__device__ int      g_idx[N_ROWS];
__device__ int      g_amb[AMB_CAP];
__device__ int      g_amb_count;

// smem word offsets
#define OFF_XSQ  0          // 64 d4 x 68 = 4352 w
#define OFF_ESQ  4352       // 64 d4 x 64 codes = 4096 w
#define OFF_SN   8448       // 64
#define OFF_RV   8512       // 1024
#define OFF_RS   9536       // 1024
#define OFF_RI   10560      // 1024
#define OFF_LRED 11584      // 8
#define SMEM_FLOATS 11592
#define SMEM_BYTES  (SMEM_FLOATS * 4)

__device__ __forceinline__ int q8(float v) {
    int q = __float2int_rn(v * QS);
    return max(-127, min(127, q));
}
__device__ __forceinline__ uint32_t pack4(float a, float b, float c, float d) {
    return (uint32_t)(q8(a) & 0xFF) | ((uint32_t)(q8(b) & 0xFF) << 8) |
           ((uint32_t)(q8(c) & 0xFF) << 16) | ((uint32_t)(q8(d) & 0xFF) << 24);
}

// ---------------------------------------------------------------------------
// prep: 0-255 transpose eT; 256-259 norms+reset; 260-323 pack e_q.
__global__ void vq_prep(const float* __restrict__ e) {
    int b = blockIdx.x;
    if (b < 256) {
        int d = b;
        for (int k = threadIdx.x; k < K_CODES; k += 256)
            g_eT[k * DIM + d] = e[d * K_CODES + k];
    } else if (b < 260) {
        int k = (b - 256) * 256 + threadIdx.x;
        double s = 0.0;
        for (int d = 0; d < DIM; d++) {
            double v = (double)e[d * K_CODES + k];
            s += v * v;
        }
        g_enorm[k]   = (float)s;
        g_enorm_d[k] = s;
        if (b == 256 && threadIdx.x == 0) {
            g_loss_acc = 0.0; g_amb_count = 0;
        }
    } else {
        int d4 = b - 260;                  // 0..63
        for (int k = threadIdx.x; k < K_CODES; k += 256) {
            g_eq[d4 * K_CODES + k] = pack4(
                e[(size_t)(4 * d4 + 0) * K_CODES + k],
                e[(size_t)(4 * d4 + 1) * K_CODES + k],
                e[(size_t)(4 * d4 + 2) * K_CODES + k],
                e[(size_t)(4 * d4 + 3) * K_CODES + k]);
        }
    }
}

// ---------------------------------------------------------------------------
__global__ void __launch_bounds__(256) vq_main(const float* __restrict__ x,
                                               float* __restrict__ out) {
    extern __shared__ float sm[];
    uint32_t* xsq  = (uint32_t*)(sm + OFF_XSQ);   // [d4][row]
    uint32_t* esq  = (uint32_t*)(sm + OFF_ESQ);   // [d4][code]
    float*    snorm = sm + OFF_SN;
    float*    rv   = sm + OFF_RV;
    float*    rs   = sm + OFF_RS;
    int*      ri   = (int*)(sm + OFF_RI);
    float*    lred = sm + OFF_LRED;

    const int tid  = threadIdx.x;
    const int lane = tid & 31;
    const int wid  = tid >> 5;
    const int tx   = tid & 15;
    const int ty   = tid >> 4;
    const int tx4  = tx * 4;
    const int ty4  = ty * 4;
    const int row0 = blockIdx.x * BM;
    const float* xblk = x + (size_t)row0 * DIM;

    // ---- stage x tile quantized [d4][row] ----
    #pragma unroll
    for (int it = 0; it < 16; it++) {
        int i  = it * 256 + tid;
        int r  = i >> 6;          // 0..63
        int d4 = i & 63;
        float4 v = ((const float4*)(xblk + (size_t)r * DIM))[d4];
        xsq[d4 * XQSTR + r] = pack4(v.x, v.y, v.z, v.w);
    }

    float bestv[4], secv[4];
    int   besti[4];
    #pragma unroll
    for (int i = 0; i < 4; i++) { bestv[i] = 3.4e38f; secv[i] = 3.4e38f; besti[i] = 0; }

    uint4 pf[4];
    const int pd4 = tid >> 2, pcq = (tid & 3) * 16;

    // prefetch tile 0: codes pcq..pcq+15 of d4-row pd4
    {
        const uint4* p = (const uint4*)&g_eq[(size_t)pd4 * K_CODES + pcq];
        pf[0] = p[0]; pf[1] = p[1]; pf[2] = p[2]; pf[3] = p[3];
    }

    for (int t = 0; t < 16; t++) {
        const int c0 = t * 64;

        __syncthreads();
        {
            uint4* q = (uint4*)&esq[pd4 * 64 + pcq];
            q[0] = pf[0]; q[1] = pf[1]; q[2] = pf[2]; q[3] = pf[3];
        }
        if (tid < 64) snorm[tid] = g_enorm[c0 + tid];

        if (t + 1 < 16) {
            const uint4* p = (const uint4*)&g_eq[
                (size_t)pd4 * K_CODES + (t + 1) * 64 + pcq];
            pf[0] = p[0]; pf[1] = p[1]; pf[2] = p[2]; pf[3] = p[3];
        }
        __syncthreads();

        int acc[4][4];
        #pragma unroll
        for (int i = 0; i < 4; i++)
            #pragma unroll
            for (int j = 0; j < 4; j++) acc[i][j] = 0;

        #pragma unroll 8
        for (int d4 = 0; d4 < 64; d4++) {
            uint4 au = *(const uint4*)&xsq[d4 * XQSTR + ty4];
            uint4 bu = *(const uint4*)&esq[d4 * 64 + tx4];
            int a0 = (int)au.x, a1 = (int)au.y, a2 = (int)au.z, a3 = (int)au.w;
            int b0 = (int)bu.x, b1 = (int)bu.y, b2 = (int)bu.z, b3 = (int)bu.w;
            acc[0][0] = __dp4a(a0, b0, acc[0][0]); acc[0][1] = __dp4a(a0, b1, acc[0][1]);
            acc[0][2] = __dp4a(a0, b2, acc[0][2]); acc[0][3] = __dp4a(a0, b3, acc[0][3]);
            acc[1][0] = __dp4a(a1, b0, acc[1][0]); acc[1][1] = __dp4a(a1, b1, acc[1][1]);
            acc[1][2] = __dp4a(a1, b2, acc[1][2]); acc[1][3] = __dp4a(a1, b3, acc[1][3]);
            acc[2][0] = __dp4a(a2, b0, acc[2][0]); acc[2][1] = __dp4a(a2, b1, acc[2][1]);
            acc[2][2] = __dp4a(a2, b2, acc[2][2]); acc[2][3] = __dp4a(a2, b3, acc[2][3]);
            acc[3][0] = __dp4a(a3, b0, acc[3][0]); acc[3][1] = __dp4a(a3, b1, acc[3][1]);
            acc[3][2] = __dp4a(a3, b2, acc[3][2]); acc[3][3] = __dp4a(a3, b3, acc[3][3]);
        }

        #pragma unroll
        for (int j = 0; j < 4; j++) {
            float n = snorm[tx4 + j];
            int  ci = c0 + tx4 + j;
            #pragma unroll
            for (int i = 0; i < 4; i++) {
                float dist = fmaf(-SCALE2, (float)acc[i][j], n);
                if (dist < bestv[i]) {
                    secv[i] = bestv[i]; bestv[i] = dist; besti[i] = ci;
                } else if (dist < secv[i]) {
                    secv[i] = dist;
                }
            }
        }
    }

    // ---- cross-tx reduce per row ----
    __syncthreads();
    #pragma unroll
    for (int i = 0; i < 4; i++) {
        int row = ty4 + i;
        rv[row * 16 + tx] = bestv[i];
        rs[row * 16 + tx] = secv[i];
        ri[row * 16 + tx] = besti[i];
    }
    __syncthreads();
    if (tid < BM) {
        int row = tid;
        float m1v = 3.4e38f, m2v = 3.4e38f;
        int m1i = 0;
        #pragma unroll
        for (int t = 0; t < 16; t++) {
            float v  = rv[row * 16 + t];
            int   i2 = ri[row * 16 + t];
            float s2 = rs[row * 16 + t];
            if (v < m1v) {
                if (m1v < m2v) m2v = m1v;
                m1v = v; m1i = i2;
            } else if (v < m2v) m2v = v;
            if (s2 < m2v) m2v = s2;
        }
        m1i &= (K_CODES - 1);
        int grow = row0 + row;
        g_idx[grow] = m1i;
        ri[row * 16] = m1i;
        if (!(m2v - m1v >= FLAG_THR)) {   // NaN-safe
            int slot = atomicAdd(&g_amb_count, 1);
            if (slot < AMB_CAP) g_amb[slot] = grow;
        }
    }
    __syncthreads();

    // ---- gather + straight-through output + loss (original fp32) ----
    float local = 0.f;
    #pragma unroll
    for (int rr = 0; rr < BM / 8; rr++) {
        int row = wid * 8 + rr;
        int idx = ri[row * 16] & (K_CODES - 1);
        const float* esrc = g_eT + (size_t)idx * DIM;
        const float* xrow = xblk + (size_t)row * DIM;
        float* orow = out + (size_t)(row0 + row) * DIM;
        #pragma unroll
        for (int kk = 0; kk < 8; kk++) {
            int d = kk * 32 + lane;
            float q  = esrc[d];
            float xv = xrow[d];
            float dq = q - xv;
            local += dq * dq;
            orow[d] = xv + dq;
        }
    }
    #pragma unroll
    for (int off = 16; off; off >>= 1)
        local += __shfl_xor_sync(0xffffffffu, local, off);
    if (lane == 0) lred[wid] = local;
    __syncthreads();
    if (tid == 0) {
        float ssum = 0.f;
        #pragma unroll
        for (int w = 0; w < 8; w++) ssum += lred[w];
        atomicAdd(&g_loss_acc, (double)ssum);
    }
}

// ---------------------------------------------------------------------------
// vq_fix batched: RB flagged rows share one pass over e. Tier-1 fp32; tier-2
// compensated + TIE_EPS window per near-tie row only. Patch out + loss.
__global__ void __launch_bounds__(256) vq_fix(const float* __restrict__ x,
                                              const float* __restrict__ e,
                                              float* __restrict__ out) {
    __shared__ float  xr[RB * DIM];
    __shared__ int    rows_s[RB];
    __shared__ float  frb[256], frs[256];
    __shared__ int    fri[256];
    __shared__ double sdd[256];
    __shared__ double svv[256];
    __shared__ int    sii[256];
    __shared__ double s_minv;

    const int tid = threadIdx.x;
    int total = g_amb_count; if (total > AMB_CAP) total = AMB_CAP;
    int ngroups = (total + RB - 1) / RB;

    for (int grp = blockIdx.x; grp < ngroups; grp += gridDim.x) {
        int base = grp * RB;
        int rcnt = total - base; if (rcnt > RB) rcnt = RB;

        if (tid < RB) rows_s[tid] = g_amb[base + (tid < rcnt ? tid : 0)];
        __syncthreads();
        for (int i = tid; i < RB * DIM; i += 256) {
            int r = i >> 8;
            xr[i] = (r < rcnt) ? x[(size_t)rows_s[r] * DIM + (i & 255)] : 0.f;
        }
        __syncthreads();

        // tier 1: shared e-stream, RB rows x 4 codes per thread
        float acc[RB][4];
        #pragma unroll
        for (int r = 0; r < RB; r++)
            #pragma unroll
            for (int j = 0; j < 4; j++) acc[r][j] = 0.f;

        const float* ebase = e + (size_t)tid * 4;
        #pragma unroll 4
        for (int d = 0; d < DIM; d++) {
            float4 ev = *(const float4*)(ebase + (size_t)d * K_CODES);
            #pragma unroll
            for (int r = 0; r < RB; r++) {
                float xv = xr[r * DIM + d];
                acc[r][0] = fmaf(xv, ev.x, acc[r][0]);
                acc[r][1] = fmaf(xv, ev.y, acc[r][1]);
                acc[r][2] = fmaf(xv, ev.z, acc[r][2]);
                acc[r][3] = fmaf(xv, ev.w, acc[r][3]);
            }
        }

        for (int r = 0; r < rcnt; r++) {
            int row = rows_s[r];
            float dj[4];
            #pragma unroll
            for (int j = 0; j < 4; j++)
                dj[j] = fmaf(-2.f, acc[r][j], g_enorm[tid * 4 + j]);

            float b = 3.4e38f, sv = 3.4e38f; int bi = 0;
            #pragma unroll
            for (int j = 0; j < 4; j++) {
                int k = tid * 4 + j;
                if (dj[j] < b) { sv = b; b = dj[j]; bi = k; }
                else if (dj[j] < sv) sv = dj[j];
            }
            frb[tid] = b; frs[tid] = sv; fri[tid] = bi;
            __syncthreads();
            for (int off = 128; off; off >>= 1) {
                if (tid < off) {
                    float b2 = frb[tid + off], s2v = frs[tid + off];
                    int   i2 = fri[tid + off];
                    float b1 = frb[tid], s1v = frs[tid];
                    int   i1 = fri[tid];
                    if (b2 < b1 || (b2 == b1 && i2 < i1)) {
                        frb[tid] = b2; fri[tid] = i2; frs[tid] = fminf(b1, s2v);
                    } else {
                        frs[tid] = fminf(s1v, b2);
                    }
                }
                __syncthreads();
            }
            float margin = frs[0] - frb[0];
            int newIdx = fri[0] & (K_CODES - 1);
            __syncthreads();

            if (!(margin >= 1e-3f)) {     // tier 2 — rare
                sdd[tid] = (double)xr[r * DIM + tid] * (double)xr[r * DIM + tid];
                __syncthreads();
                for (int off = 128; off; off >>= 1) {
                    if (tid < off) sdd[tid] += sdd[tid + off];
                    __syncthreads();
                }
                double xn = sdd[0];
                __syncthreads();

                float s[4] = {0.f, 0.f, 0.f, 0.f};
                float c[4] = {0.f, 0.f, 0.f, 0.f};
                #pragma unroll 4
                for (int d = 0; d < DIM; d++) {
                    float xv = xr[r * DIM + d];
                    float4 ev = *(const float4*)(ebase + (size_t)d * K_CODES);
                    float evs[4] = {ev.x, ev.y, ev.z, ev.w};
                    #pragma unroll
                    for (int j = 0; j < 4; j++) {
                        float p  = xv * evs[j];
                        float e1 = fmaf(xv, evs[j], -p);
                        float t  = s[j] + p;
                        float z  = t - s[j];
                        float e2 = (s[j] - (t - z)) + (p - z);
                        s[j] = t; c[j] += e1 + e2;
                    }
                }
                double dist[4];
                #pragma unroll
                for (int j = 0; j < 4; j++)
                    dist[j] = xn + g_enorm_d[tid * 4 + j]
                            - 2.0 * ((double)s[j] + (double)c[j]);

                double bv = 1e300; int bi2 = 0x7fffffff;
                #pragma unroll
                for (int j = 0; j < 4; j++) {
                    int k = tid * 4 + j;
                    if (dist[j] < bv || (dist[j] == bv && k < bi2)) { bv = dist[j]; bi2 = k; }
                }
                svv[tid] = bv; sii[tid] = bi2;
                __syncthreads();
                for (int off = 128; off; off >>= 1) {
                    if (tid < off) {
                        double v2 = svv[tid + off]; int i2 = sii[tid + off];
                        if (v2 < svv[tid] || (v2 == svv[tid] && i2 < sii[tid])) {
                            svv[tid] = v2; sii[tid] = i2;
                        }
                    }
                    __syncthreads();
                }
                if (tid == 0) s_minv = svv[0];
                __syncthreads();
                double minv = s_minv;

                int cand = 0x7fffffff;
                #pragma unroll
                for (int j = 0; j < 4; j++) {
                    int k = tid * 4 + j;
                    if (dist[j] <= minv + TIE_EPS && k < cand) cand = k;
                }
                sii[tid] = cand;
                __syncthreads();
                for (int off = 128; off; off >>= 1) {
                    if (tid < off) { if (sii[tid + off] < sii[tid]) sii[tid] = sii[tid + off]; }
                    __syncthreads();
                }
                newIdx = sii[0] & (K_CODES - 1);
                __syncthreads();
            }

            int oldIdx = g_idx[row];
            if (newIdx != oldIdx) {   // uniform across block
                float xv = xr[r * DIM + tid];
                float qn = g_eT[(size_t)newIdx * DIM + tid];
                float qo = g_eT[(size_t)oldIdx * DIM + tid];
                out[(size_t)row * DIM + tid] = xv + (qn - xv);
                double dn = (double)(qn - xv), dl = (double)(qo - xv);
                sdd[tid] = dn * dn - dl * dl;
                __syncthreads();
                for (int off = 128; off; off >>= 1) {
                    if (tid < off) sdd[tid] += sdd[tid + off];
                    __syncthreads();
                }
                if (tid == 0) atomicAdd(&g_loss_acc, sdd[0]);
            }
            __syncthreads();
        }
    }
}

// ---------------------------------------------------------------------------
__global__ void vq_finish(float* __restrict__ out) {
    const double nd = (double)N_ROWS * (double)DIM;
    out[(size_t)N_ROWS * DIM] = (float)(1.25 * g_loss_acc / nd);
}

// ---------------------------------------------------------------------------
extern "C" void kernel_launch(void* const* d_in, const int* in_sizes, int n_in,
                              void* d_out, int out_size) {
    const float* x = (const float*)d_in[0];
    const float* e = (const float*)d_in[1];
    if (n_in >= 2 && in_sizes[0] == K_CODES * DIM && in_sizes[1] == N_ROWS * DIM) {
        e = (const float*)d_in[0];
        x = (const float*)d_in[1];
    }
    float* out = (float*)d_out;

    cudaFuncSetAttribute(vq_main, cudaFuncAttributeMaxDynamicSharedMemorySize, SMEM_BYTES);

    vq_prep<<<324, 256>>>(e);
    vq_main<<<N_ROWS / BM, 256, SMEM_BYTES>>>(x, out);
    vq_fix<<<2048, 256>>>(x, e, out);
    if (out_size > N_ROWS * DIM) vq_finish<<<1, 1>>>(out);
}